// round 13
// baseline (speedup 1.0000x reference)
#include <cuda_runtime.h>
#include <cuda_bf16.h>
#include <math.h>

#define KDIR 6
#define LL 4096
#define DI 128
#define NS 16
#define DTR 4
#define NCH (KDIR * DI)
#define CHK 64
#define LC  (LL / CHK)         // 64

// ---------------- scratch ----------------
__device__ float  g_xx[LL * DI];
__device__ float  g_z [LL * DI];
__device__ float  g_xcT[LL * DI];
__device__ float2 g_BC[KDIR * LL * NS];   // (B,C), [k][t][n] interleaved
__device__ float2 g_dd[KDIR * DI * LL];   // (delta, delta*u), [k][d][t]
__device__ float  g_y [KDIR * LL * DI];   // [k][t][d]
__device__ float2 g_chk [NCH * CHK * NS]; // per-chunk (xf, aprod)

// ---------------- closed-form diagonal permutation ----------------
__device__ __forceinline__ int dg_low(int r) {
    int dg = (int)((sqrtf((float)(8 * r + 1)) - 1.f) * 0.5f);
    while (((dg + 1) * (dg + 2)) >> 1 <= r) dg++;
    while ((dg * (dg + 1)) >> 1 > r) dg--;
    return dg;
}
__device__ __forceinline__ int diag_t(int r) {
    int i, dg;
    if (r < 2080) { dg = dg_low(r); i = r - ((dg * (dg + 1)) >> 1); }
    else {
        int q = 4095 - r;
        int dgm = dg_low(q);
        int p = q - ((dgm * (dgm + 1)) >> 1);
        i = 63 - p;
        dg = 126 - dgm;
    }
    int j = dg - i;
    return (i << 6) | j;
}
__device__ __forceinline__ int rev_idx(int t) {
    int i = t >> 6, c = t & 63, dg = i + c;
    int cum = (dg < 64) ? ((dg * (dg + 1)) >> 1)
                        : 4096 - (((127 - dg) * (128 - dg)) >> 1);
    int lo = dg - 63; if (lo < 0) lo = 0;
    return cum + i - lo;
}
__device__ __forceinline__ int sin_idx(int k, int t) {
    switch (k) {
        case 0: return t;
        case 1: return ((t & 63) << 6) | (t >> 6);
        case 2: return 4095 - t;
        case 3: { int t2 = 4095 - t; return ((t2 & 63) << 6) | (t2 >> 6); }
        case 4: return diag_t(t);
        default: return diag_t(t) ^ 63;
    }
}
__device__ __forceinline__ int iout_idx(int k, int j) {
    switch (k) {
        case 0: return j;
        case 1: return ((j & 63) << 6) | (j >> 6);
        case 2: return 4095 - j;
        case 3: return 4095 - (((j & 63) << 6) | (j >> 6));
        case 4: return rev_idx(j);
        default: return rev_idx(4095 - j);
    }
}

// ---------------- in_proj GEMM: blockIdx.y = output half ----------------
__global__ void __launch_bounds__(256) k_inproj(const float* __restrict__ x,
                                                const float* __restrict__ W_in) {
    __shared__ float Wsm[128 * 65];
    __shared__ float xsm[32 * 65];
    int tid = threadIdx.x;
    int l0 = blockIdx.x * 32;
    int ot = blockIdx.y;
    for (int i = tid; i < 32 * 64; i += 256)
        xsm[(i >> 6) * 65 + (i & 63)] = x[(l0 + (i >> 6)) * 64 + (i & 63)];
    for (int i = tid; i < 128 * 64; i += 256)
        Wsm[(i >> 6) * 65 + (i & 63)] = W_in[(ot * 128 + (i >> 6)) * 64 + (i & 63)];
    int og = tid & 31;
    int lg = tid >> 5;
    __syncthreads();
    float acc[4][4];
    #pragma unroll
    for (int i = 0; i < 4; i++)
        #pragma unroll
        for (int ii = 0; ii < 4; ii++) acc[i][ii] = 0.f;
    for (int c = 0; c < 64; c++) {
        float wv[4], xv[4];
        #pragma unroll
        for (int i = 0; i < 4; i++)  wv[i]  = Wsm[(og + 32 * i) * 65 + c];
        #pragma unroll
        for (int ii = 0; ii < 4; ii++) xv[ii] = xsm[(lg + 8 * ii) * 65 + c];
        #pragma unroll
        for (int i = 0; i < 4; i++)
            #pragma unroll
            for (int ii = 0; ii < 4; ii++)
                acc[i][ii] = fmaf(wv[i], xv[ii], acc[i][ii]);
    }
    float* dst = (ot == 0) ? g_xx : g_z;
    #pragma unroll
    for (int i = 0; i < 4; i++)
        #pragma unroll
        for (int ii = 0; ii < 4; ii++)
            dst[(l0 + lg + 8 * ii) * 128 + og + 32 * i] = acc[i][ii];
}

// ---------------- depthwise 3x3 conv + bias + SiLU (float4 per thread) ----------------
__global__ void __launch_bounds__(256) k_conv(const float* __restrict__ conv_w,
                                              const float* __restrict__ conv_b) {
    __shared__ float4 cw[9 * 32];
    __shared__ float4 cb[32];
    int tid = threadIdx.x;
    for (int i = tid; i < 9 * 32; i += 256) {
        int tap = i >> 5, d4 = i & 31;
        cw[i] = make_float4(conv_w[(4 * d4 + 0) * 9 + tap], conv_w[(4 * d4 + 1) * 9 + tap],
                            conv_w[(4 * d4 + 2) * 9 + tap], conv_w[(4 * d4 + 3) * 9 + tap]);
    }
    if (tid < 32) cb[tid] = ((const float4*)conv_b)[tid];
    __syncthreads();
    int idx = blockIdx.x * 256 + tid;    // < LL*32
    int d4 = idx & 31;
    int l = idx >> 5;
    int h = l >> 6, w = l & 63;
    float4 acc = cb[d4];
    const float4* xx4 = (const float4*)g_xx;
    #pragma unroll
    for (int kh = -1; kh <= 1; kh++) {
        int hh = h + kh;
        if ((unsigned)hh >= 64u) continue;
        #pragma unroll
        for (int kw = -1; kw <= 1; kw++) {
            int wc = w + kw;
            if ((unsigned)wc >= 64u) continue;
            float4 v = xx4[((hh << 6) | wc) * 32 + d4];
            float4 cc = cw[((kh + 1) * 3 + (kw + 1)) * 32 + d4];
            acc.x = fmaf(cc.x, v.x, acc.x);
            acc.y = fmaf(cc.y, v.y, acc.y);
            acc.z = fmaf(cc.z, v.z, acc.z);
            acc.w = fmaf(cc.w, v.w, acc.w);
        }
    }
    acc.x = acc.x / (1.f + __expf(-acc.x));
    acc.y = acc.y / (1.f + __expf(-acc.y));
    acc.z = acc.z / (1.f + __expf(-acc.z));
    acc.w = acc.w / (1.f + __expf(-acc.w));
    ((float4*)g_xcT)[l * 32 + d4] = acc;
}

// ---------------- projection + fused delta ----------------
__global__ void __launch_bounds__(256) k_proj(const float* __restrict__ x_proj_w,
                                              const float* __restrict__ dt_w,
                                              const float* __restrict__ dt_b) {
    __shared__ float xs[32][129];
    __shared__ __align__(16) float Ps[36 * 128];
    __shared__ float dts[4][32];
    __shared__ int sidx[32];
    int k  = blockIdx.y;
    int t0 = blockIdx.x * 32;
    int tid = threadIdx.x;
    if (tid < 32) sidx[tid] = sin_idx(k, t0 + tid);
    __syncthreads();
    for (int i = tid; i < 36 * 128; i += 256)
        Ps[i] = x_proj_w[k * 36 * 128 + i];
    {
        int lane = tid & 31;
        for (int r = tid >> 5; r < 32; r += 8) {
            int s = sidx[r];
            const float4* src = (const float4*)(g_xcT + s * 128);
            float4 v = src[lane];
            xs[r][lane * 4 + 0] = v.x;
            xs[r][lane * 4 + 1] = v.y;
            xs[r][lane * 4 + 2] = v.z;
            xs[r][lane * 4 + 3] = v.w;
        }
    }
    __syncthreads();
    if (tid < 192) {
        int cg = tid >> 4;
        int tg = tid & 15;
        float acc[3][2] = {{0.f,0.f},{0.f,0.f},{0.f,0.f}};
        const float4* Ps4 = (const float4*)Ps;
        const float* r0 = &xs[tg * 2 + 0][0];
        const float* r1 = &xs[tg * 2 + 1][0];
        for (int dd4 = 0; dd4 < 32; dd4++) {
            float4 a0 = Ps4[(cg * 3 + 0) * 32 + dd4];
            float4 a1 = Ps4[(cg * 3 + 1) * 32 + dd4];
            float4 a2 = Ps4[(cg * 3 + 2) * 32 + dd4];
            float b00 = r0[dd4 * 4 + 0], b01 = r0[dd4 * 4 + 1];
            float b02 = r0[dd4 * 4 + 2], b03 = r0[dd4 * 4 + 3];
            float b10 = r1[dd4 * 4 + 0], b11 = r1[dd4 * 4 + 1];
            float b12 = r1[dd4 * 4 + 2], b13 = r1[dd4 * 4 + 3];
            acc[0][0] = fmaf(a0.x, b00, fmaf(a0.y, b01, fmaf(a0.z, b02, fmaf(a0.w, b03, acc[0][0]))));
            acc[0][1] = fmaf(a0.x, b10, fmaf(a0.y, b11, fmaf(a0.z, b12, fmaf(a0.w, b13, acc[0][1]))));
            acc[1][0] = fmaf(a1.x, b00, fmaf(a1.y, b01, fmaf(a1.z, b02, fmaf(a1.w, b03, acc[1][0]))));
            acc[1][1] = fmaf(a1.x, b10, fmaf(a1.y, b11, fmaf(a1.z, b12, fmaf(a1.w, b13, acc[1][1]))));
            acc[2][0] = fmaf(a2.x, b00, fmaf(a2.y, b01, fmaf(a2.z, b02, fmaf(a2.w, b03, acc[2][0]))));
            acc[2][1] = fmaf(a2.x, b10, fmaf(a2.y, b11, fmaf(a2.z, b12, fmaf(a2.w, b13, acc[2][1]))));
        }
        #pragma unroll
        for (int i = 0; i < 3; i++)
            #pragma unroll
            for (int j = 0; j < 2; j++) {
                int c = cg * 3 + i;
                int tl = tg * 2 + j;
                int t = t0 + tl;
                float v = acc[i][j];
                if (c < 4)       dts[c][tl] = v;
                else if (c < 20) g_BC[(size_t)(k * LL + t) * NS + (c - 4)].x = v;
                else             g_BC[(size_t)(k * LL + t) * NS + (c - 20)].y = v;
            }
    }
    __syncthreads();
    {
        int t = tid & 31;
        int w = tid >> 5;
        #pragma unroll
        for (int it = 0; it < 16; it++) {
            int d = w + 8 * it;
            float acc = dt_b[k * 128 + d];
            #pragma unroll
            for (int r = 0; r < 4; r++)
                acc = fmaf(dt_w[(k * 128 + d) * 4 + r], dts[r][t], acc);
            float delta = (acc > 20.f) ? acc : log1pf(__expf(acc));
            float u = xs[t][d];
            g_dd[(size_t)(k * 128 + d) * LL + t0 + t] = make_float2(delta, delta * u);
        }
    }
}

// ---------------- scan pass 1: smem B [t][n], float4 dd ----------------
__global__ void __launch_bounds__(512) k_scan1(const float* __restrict__ A_logs) {
    __shared__ float bb[LC * 16];          // 4 KB, [t][n]
    int tid = threadIdx.x;
    int wl = tid >> 5;
    int ln = tid & 31;
    int k = blockIdx.z, chunk = blockIdx.y, xh = blockIdx.x;
    int dp = xh * 16 + wl;
    int half = ln >> 4, n = ln & 15;
    int d = dp + (half << 6);
    int ch = k * 128 + d;
    int tbeg = chunk * LC;

    {
        const float4* src4 = (const float4*)(g_BC + (size_t)(k * LL + tbeg) * NS);
        if (tid < 512) {
            float4 v = src4[tid];
            bb[2 * tid]     = v.x;
            bb[2 * tid + 1] = v.z;
        }
    }
    __syncthreads();

    const float4* pDD4 = (const float4*)(g_dd + (size_t)ch * LL + tbeg);
    float cA = -expf(A_logs[ch * 16 + n]) * 1.44269504f;
    float x = 0.f, sdelta = 0.f;
    #pragma unroll 4
    for (int s2 = 0; s2 < LC / 2; s2++) {
        float4 q = pDD4[s2];
        float b0 = bb[(2 * s2) * 16 + n];
        float b1 = bb[(2 * s2 + 1) * 16 + n];
        float dA;
        asm("ex2.approx.ftz.f32 %0, %1;" : "=f"(dA) : "f"(q.x * cA));
        x = fmaf(dA, x, q.y * b0);
        asm("ex2.approx.ftz.f32 %0, %1;" : "=f"(dA) : "f"(q.z * cA));
        x = fmaf(dA, x, q.w * b1);
        sdelta += q.x + q.z;
    }
    float ap;
    asm("ex2.approx.ftz.f32 %0, %1;" : "=f"(ap) : "f"(sdelta * cA));
    g_chk[((size_t)ch * CHK + chunk) * NS + n] = make_float2(x, ap);
}

// ---------------- scan pass 3: inline prefix fold + batched loads ----------------
__global__ void __launch_bounds__(512) k_scan3(const float* __restrict__ A_logs) {
    __shared__ __align__(16) float BsmT[16 * 76];
    __shared__ __align__(16) float CsmT[16 * 76];
    __shared__ float xc[16][8][33];        // 16.9 KB
    __shared__ float ytile[8 * 33];
    int tid = threadIdx.x;
    int wl = tid >> 5;                     // 0..15
    int ln = tid & 31;
    int k = blockIdx.z, chunk = blockIdx.y, xh = blockIdx.x;
    int dp = xh * 16 + wl;
    int half = ln >> 4, n = ln & 15;
    int d = dp + (half << 6);
    int ch = k * 128 + d;
    int tbeg = chunk * LC;

    {
        const float2* srcBC = g_BC + (size_t)(k * LL + tbeg) * NS;
        for (int i = tid; i < LC * 16; i += 512) {
            int t = i >> 4, nn = i & 15;
            float2 v = srcBC[i];
            BsmT[nn * 76 + t] = v.x;
            CsmT[nn * 76 + t] = v.y;
        }
    }
    __syncthreads();

    const float4* pDD4 = (const float4*)(g_dd + (size_t)ch * LL + tbeg);
    const float4* pB4 = (const float4*)(BsmT + n * 76);
    const float4* pC4 = (const float4*)(CsmT + n * 76);
    float cA = -expf(A_logs[ch * 16 + n]) * 1.44269504f;

    // inline prefix fold of preceding chunk summaries (replaces scan2)
    float x = 0.f;
    {
        const float2* pk = g_chk + (size_t)ch * CHK * NS + n;
        int c = 0;
        for (; c + 8 <= chunk; c += 8) {
            float2 f0 = pk[(c + 0) * NS], f1 = pk[(c + 1) * NS];
            float2 f2 = pk[(c + 2) * NS], f3 = pk[(c + 3) * NS];
            float2 f4 = pk[(c + 4) * NS], f5 = pk[(c + 5) * NS];
            float2 f6 = pk[(c + 6) * NS], f7 = pk[(c + 7) * NS];
            x = fmaf(f0.y, x, f0.x);
            x = fmaf(f1.y, x, f1.x);
            x = fmaf(f2.y, x, f2.x);
            x = fmaf(f3.y, x, f3.x);
            x = fmaf(f4.y, x, f4.x);
            x = fmaf(f5.y, x, f5.x);
            x = fmaf(f6.y, x, f6.x);
            x = fmaf(f7.y, x, f7.x);
        }
        for (; c < chunk; c++) {
            float2 f = pk[c * NS];
            x = fmaf(f.y, x, f.x);
        }
    }

    int rc = ln >> 4;
    int rj = (ln >> 1) & 7;
    int rh = ln & 1;
    int sr = tid >> 5;         // 0..15 (only 0..7 used for stores)
    int sc = tid & 31;
    int sd = xh * 16 + (sc & 15) + ((sc >> 4) << 6);
    float* ydst0 = g_y + (size_t)(k * LL + tbeg) * 128 + sd;

    for (int t0 = 0; t0 < LC; t0 += 8) {
        float4 q0 = pDD4[(t0 >> 1) + 0];
        float4 q1 = pDD4[(t0 >> 1) + 1];
        float4 q2 = pDD4[(t0 >> 1) + 2];
        float4 q3 = pDD4[(t0 >> 1) + 3];
        float4 b40 = pB4[(t0 >> 2) + 0];
        float4 b41 = pB4[(t0 >> 2) + 1];
        float4 c40 = pC4[(t0 >> 2) + 0];
        float4 c41 = pC4[(t0 >> 2) + 1];
        float dA;
        asm("ex2.approx.ftz.f32 %0, %1;" : "=f"(dA) : "f"(q0.x * cA));
        x = fmaf(dA, x, q0.y * b40.x);
        xc[wl][0][ln] = x * c40.x;
        asm("ex2.approx.ftz.f32 %0, %1;" : "=f"(dA) : "f"(q0.z * cA));
        x = fmaf(dA, x, q0.w * b40.y);
        xc[wl][1][ln] = x * c40.y;
        asm("ex2.approx.ftz.f32 %0, %1;" : "=f"(dA) : "f"(q1.x * cA));
        x = fmaf(dA, x, q1.y * b40.z);
        xc[wl][2][ln] = x * c40.z;
        asm("ex2.approx.ftz.f32 %0, %1;" : "=f"(dA) : "f"(q1.z * cA));
        x = fmaf(dA, x, q1.w * b40.w);
        xc[wl][3][ln] = x * c40.w;
        asm("ex2.approx.ftz.f32 %0, %1;" : "=f"(dA) : "f"(q2.x * cA));
        x = fmaf(dA, x, q2.y * b41.x);
        xc[wl][4][ln] = x * c41.x;
        asm("ex2.approx.ftz.f32 %0, %1;" : "=f"(dA) : "f"(q2.z * cA));
        x = fmaf(dA, x, q2.w * b41.y);
        xc[wl][5][ln] = x * c41.y;
        asm("ex2.approx.ftz.f32 %0, %1;" : "=f"(dA) : "f"(q3.x * cA));
        x = fmaf(dA, x, q3.y * b41.z);
        xc[wl][6][ln] = x * c41.z;
        asm("ex2.approx.ftz.f32 %0, %1;" : "=f"(dA) : "f"(q3.z * cA));
        x = fmaf(dA, x, q3.w * b41.w);
        xc[wl][7][ln] = x * c41.w;
        __syncwarp();
        float sum = 0.f;
        #pragma unroll
        for (int m = 0; m < 8; m++)
            sum += xc[wl][rj][rc * 16 + rh * 8 + m];
        sum += __shfl_xor_sync(0xffffffffu, sum, 1);
        if (rh == 0) ytile[rj * 33 + rc * 16 + wl] = sum;
        __syncthreads();
        if (tid < 256) ydst0[(size_t)(t0 + sr) * 128] = ytile[sr * 33 + sc];
        __syncthreads();
    }
}

// ---------------- combine: 4 concurrent positions per block ----------------
__global__ void __launch_bounds__(512) k_comb(const float* __restrict__ Ds,
                                              const float* __restrict__ ln_g,
                                              const float* __restrict__ ln_b,
                                              const float* __restrict__ W_out,
                                              float* __restrict__ out) {
    __shared__ __align__(16) float Wsm[64 * 132];
    __shared__ __align__(16) float gsm[4][132];
    __shared__ float red[4][8];
    __shared__ float mus[4][2];
    __shared__ int ism[6 * 16];
    int tid = threadIdx.x;
    int g = tid >> 7;
    int gt = tid & 127;
    for (int i = tid; i < 64 * 128; i += 512)
        Wsm[(i >> 7) * 132 + (i & 127)] = W_out[i];
    if (tid < 96) {
        int kk = tid >> 4, jj = tid & 15;
        ism[kk * 16 + jj] = iout_idx(kk, blockIdx.x * 16 + jj);
    }
    int d = gt;
    float dsum = 0.f;
    #pragma unroll
    for (int k = 0; k < 5; k++) dsum += Ds[k * 128 + d];
    float d5 = Ds[5 * 128 + d];
    float gg = ln_g[d], bb = ln_b[d];
    int lane = tid & 31;
    int wg = gt >> 5;
    int oo = (wg << 4) + (lane & 15);
    int hh2 = lane >> 4;
    __syncthreads();

    for (int it = 0; it < 4; it++) {
        int jj = it * 4 + g;
        int j = blockIdx.x * 16 + jj;
        float y = 0.f;
        #pragma unroll
        for (int k = 0; k < 6; k++)
            y += g_y[(size_t)(k * LL + ism[k * 16 + jj]) * 128 + d];
        int fl = ((63 - (j >> 6)) << 6) | (j & 63);
        y += dsum * g_xcT[j * 128 + d] + d5 * g_xcT[fl * 128 + d];
        float s1 = y, s2 = y * y;
        #pragma unroll
        for (int o = 16; o; o >>= 1) {
            s1 += __shfl_xor_sync(0xffffffffu, s1, o);
            s2 += __shfl_xor_sync(0xffffffffu, s2, o);
        }
        if (lane == 0) { red[g][wg] = s1; red[g][4 + wg] = s2; }
        __syncthreads();
        if (gt == 0) {
            float S1 = red[g][0] + red[g][1] + red[g][2] + red[g][3];
            float S2 = red[g][4] + red[g][5] + red[g][6] + red[g][7];
            float mu = S1 * (1.f / 128.f);
            float var = S2 * (1.f / 128.f) - mu * mu;
            mus[g][0] = mu;
            mus[g][1] = rsqrtf(var + 1e-5f);
        }
        __syncthreads();
        float yn = (y - mus[g][0]) * mus[g][1] * gg + bb;
        float z = g_z[j * 128 + d];
        gsm[g][d] = yn * (z / (1.f + __expf(-z)));
        __syncthreads();
        {
            float acc = 0.f;
            const float4* wrow = (const float4*)(Wsm + oo * 132 + (hh2 << 6));
            const float4* grow = (const float4*)(gsm[g] + (hh2 << 6));
            #pragma unroll
            for (int q = 0; q < 16; q++) {
                float4 wv = wrow[q];
                float4 gv = grow[q];
                acc = fmaf(wv.x, gv.x, fmaf(wv.y, gv.y, fmaf(wv.z, gv.z, fmaf(wv.w, gv.w, acc))));
            }
            acc += __shfl_xor_sync(0xffffffffu, acc, 16);
            if (hh2 == 0) out[j * 64 + oo] = acc;
        }
        __syncthreads();
    }
}

// ---------------- launch ----------------
extern "C" void kernel_launch(void* const* d_in, const int* in_sizes, int n_in,
                              void* d_out, int out_size) {
    const float* x        = (const float*)d_in[0];
    const float* W_in     = (const float*)d_in[1];
    const float* conv_w   = (const float*)d_in[2];
    const float* conv_b   = (const float*)d_in[3];
    const float* x_proj_w = (const float*)d_in[4];
    const float* dt_w     = (const float*)d_in[5];
    const float* dt_b     = (const float*)d_in[6];
    const float* A_logs   = (const float*)d_in[7];
    const float* Ds       = (const float*)d_in[8];
    const float* ln_g     = (const float*)d_in[9];
    const float* ln_b     = (const float*)d_in[10];
    const float* W_out    = (const float*)d_in[11];
    float* out = (float*)d_out;

    {
        dim3 g(128, 2);
        k_inproj<<<g, 256>>>(x, W_in);
    }
    k_conv<<<(LL * 32) / 256, 256>>>(conv_w, conv_b);
    {
        dim3 g(LL / 32, KDIR);
        k_proj<<<g, 256>>>(x_proj_w, dt_w, dt_b);
    }
    {
        dim3 gs(4, CHK, KDIR);
        k_scan1<<<gs, 512>>>(A_logs);
        k_scan3<<<gs, 512>>>(A_logs);
    }
    k_comb<<<256, 512>>>(Ds, ln_g, ln_b, W_out, out);
}

// round 14
// speedup vs baseline: 1.1349x; 1.1349x over previous
#include <cuda_runtime.h>
#include <cuda_bf16.h>
#include <cuda_fp16.h>
#include <math.h>

#define KDIR 6
#define LL 4096
#define DI 128
#define NS 16
#define DTR 4
#define NCH (KDIR * DI)
#define CHK 64
#define LC  (LL / CHK)         // 64

// ---------------- scratch ----------------
__device__ float   g_xx[LL * DI];
__device__ float   g_z [LL * DI];
__device__ float   g_xcT[LL * DI];
__device__ float2  g_BC[KDIR * LL * NS];    // (B,C), [k][t][n] interleaved
__device__ __half2 g_ddh[KDIR * DI * LL];   // (delta, delta*u) fp16, [k][d][t]
__device__ float   g_y [KDIR * LL * DI];    // [k][t][d]
__device__ float2  g_chk [NCH * CHK * NS];  // per-chunk (xf, aprod)

// ---------------- closed-form diagonal permutation ----------------
__device__ __forceinline__ int dg_low(int r) {
    int dg = (int)((sqrtf((float)(8 * r + 1)) - 1.f) * 0.5f);
    while (((dg + 1) * (dg + 2)) >> 1 <= r) dg++;
    while ((dg * (dg + 1)) >> 1 > r) dg--;
    return dg;
}
__device__ __forceinline__ int diag_t(int r) {
    int i, dg;
    if (r < 2080) { dg = dg_low(r); i = r - ((dg * (dg + 1)) >> 1); }
    else {
        int q = 4095 - r;
        int dgm = dg_low(q);
        int p = q - ((dgm * (dgm + 1)) >> 1);
        i = 63 - p;
        dg = 126 - dgm;
    }
    int j = dg - i;
    return (i << 6) | j;
}
__device__ __forceinline__ int rev_idx(int t) {
    int i = t >> 6, c = t & 63, dg = i + c;
    int cum = (dg < 64) ? ((dg * (dg + 1)) >> 1)
                        : 4096 - (((127 - dg) * (128 - dg)) >> 1);
    int lo = dg - 63; if (lo < 0) lo = 0;
    return cum + i - lo;
}
__device__ __forceinline__ int sin_idx(int k, int t) {
    switch (k) {
        case 0: return t;
        case 1: return ((t & 63) << 6) | (t >> 6);
        case 2: return 4095 - t;
        case 3: { int t2 = 4095 - t; return ((t2 & 63) << 6) | (t2 >> 6); }
        case 4: return diag_t(t);
        default: return diag_t(t) ^ 63;
    }
}
__device__ __forceinline__ int iout_idx(int k, int j) {
    switch (k) {
        case 0: return j;
        case 1: return ((j & 63) << 6) | (j >> 6);
        case 2: return 4095 - j;
        case 3: return 4095 - (((j & 63) << 6) | (j >> 6));
        case 4: return rev_idx(j);
        default: return rev_idx(4095 - j);
    }
}

// ---------------- in_proj GEMM: blockIdx.y = output half ----------------
__global__ void __launch_bounds__(256) k_inproj(const float* __restrict__ x,
                                                const float* __restrict__ W_in) {
    __shared__ float Wsm[128 * 65];
    __shared__ float xsm[32 * 65];
    int tid = threadIdx.x;
    int l0 = blockIdx.x * 32;
    int ot = blockIdx.y;
    for (int i = tid; i < 32 * 64; i += 256)
        xsm[(i >> 6) * 65 + (i & 63)] = x[(l0 + (i >> 6)) * 64 + (i & 63)];
    for (int i = tid; i < 128 * 64; i += 256)
        Wsm[(i >> 6) * 65 + (i & 63)] = W_in[(ot * 128 + (i >> 6)) * 64 + (i & 63)];
    int og = tid & 31;
    int lg = tid >> 5;
    __syncthreads();
    float acc[4][4];
    #pragma unroll
    for (int i = 0; i < 4; i++)
        #pragma unroll
        for (int ii = 0; ii < 4; ii++) acc[i][ii] = 0.f;
    for (int c = 0; c < 64; c++) {
        float wv[4], xv[4];
        #pragma unroll
        for (int i = 0; i < 4; i++)  wv[i]  = Wsm[(og + 32 * i) * 65 + c];
        #pragma unroll
        for (int ii = 0; ii < 4; ii++) xv[ii] = xsm[(lg + 8 * ii) * 65 + c];
        #pragma unroll
        for (int i = 0; i < 4; i++)
            #pragma unroll
            for (int ii = 0; ii < 4; ii++)
                acc[i][ii] = fmaf(wv[i], xv[ii], acc[i][ii]);
    }
    float* dst = (ot == 0) ? g_xx : g_z;
    #pragma unroll
    for (int i = 0; i < 4; i++)
        #pragma unroll
        for (int ii = 0; ii < 4; ii++)
            dst[(l0 + lg + 8 * ii) * 128 + og + 32 * i] = acc[i][ii];
}

// ---------------- depthwise 3x3 conv + bias + SiLU (float4 per thread) ----------------
__global__ void __launch_bounds__(256) k_conv(const float* __restrict__ conv_w,
                                              const float* __restrict__ conv_b) {
    __shared__ float4 cw[9 * 32];
    __shared__ float4 cb[32];
    int tid = threadIdx.x;
    for (int i = tid; i < 9 * 32; i += 256) {
        int tap = i >> 5, d4 = i & 31;
        cw[i] = make_float4(conv_w[(4 * d4 + 0) * 9 + tap], conv_w[(4 * d4 + 1) * 9 + tap],
                            conv_w[(4 * d4 + 2) * 9 + tap], conv_w[(4 * d4 + 3) * 9 + tap]);
    }
    if (tid < 32) cb[tid] = ((const float4*)conv_b)[tid];
    __syncthreads();
    int idx = blockIdx.x * 256 + tid;    // < LL*32
    int d4 = idx & 31;
    int l = idx >> 5;
    int h = l >> 6, w = l & 63;
    float4 acc = cb[d4];
    const float4* xx4 = (const float4*)g_xx;
    #pragma unroll
    for (int kh = -1; kh <= 1; kh++) {
        int hh = h + kh;
        if ((unsigned)hh >= 64u) continue;
        #pragma unroll
        for (int kw = -1; kw <= 1; kw++) {
            int wc = w + kw;
            if ((unsigned)wc >= 64u) continue;
            float4 v = xx4[((hh << 6) | wc) * 32 + d4];
            float4 cc = cw[((kh + 1) * 3 + (kw + 1)) * 32 + d4];
            acc.x = fmaf(cc.x, v.x, acc.x);
            acc.y = fmaf(cc.y, v.y, acc.y);
            acc.z = fmaf(cc.z, v.z, acc.z);
            acc.w = fmaf(cc.w, v.w, acc.w);
        }
    }
    acc.x = acc.x / (1.f + __expf(-acc.x));
    acc.y = acc.y / (1.f + __expf(-acc.y));
    acc.z = acc.z / (1.f + __expf(-acc.z));
    acc.w = acc.w / (1.f + __expf(-acc.w));
    ((float4*)g_xcT)[l * 32 + d4] = acc;
}

// ---------------- projection + fused delta (half2 dd output) ----------------
__global__ void __launch_bounds__(256) k_proj(const float* __restrict__ x_proj_w,
                                              const float* __restrict__ dt_w,
                                              const float* __restrict__ dt_b) {
    __shared__ float xs[32][129];
    __shared__ __align__(16) float Ps[36 * 128];
    __shared__ float dts[4][32];
    __shared__ float dtw[128 * 4];
    __shared__ float dtb[128];
    __shared__ int sidx[32];
    int k  = blockIdx.y;
    int t0 = blockIdx.x * 32;
    int tid = threadIdx.x;
    if (tid < 32) sidx[tid] = sin_idx(k, t0 + tid);
    __syncthreads();
    for (int i = tid; i < 36 * 128; i += 256)
        Ps[i] = x_proj_w[k * 36 * 128 + i];
    for (int i = tid; i < 512; i += 256)
        dtw[i] = dt_w[k * 512 + i];
    if (tid < 128) dtb[tid] = dt_b[k * 128 + tid];
    {
        int lane = tid & 31;
        for (int r = tid >> 5; r < 32; r += 8) {
            int s = sidx[r];
            const float4* src = (const float4*)(g_xcT + s * 128);
            float4 v = src[lane];
            xs[r][lane * 4 + 0] = v.x;
            xs[r][lane * 4 + 1] = v.y;
            xs[r][lane * 4 + 2] = v.z;
            xs[r][lane * 4 + 3] = v.w;
        }
    }
    __syncthreads();
    if (tid < 192) {
        int cg = tid >> 4;
        int tg = tid & 15;
        float acc[3][2] = {{0.f,0.f},{0.f,0.f},{0.f,0.f}};
        const float4* Ps4 = (const float4*)Ps;
        const float* r0 = &xs[tg * 2 + 0][0];
        const float* r1 = &xs[tg * 2 + 1][0];
        for (int dd4 = 0; dd4 < 32; dd4++) {
            float4 a0 = Ps4[(cg * 3 + 0) * 32 + dd4];
            float4 a1 = Ps4[(cg * 3 + 1) * 32 + dd4];
            float4 a2 = Ps4[(cg * 3 + 2) * 32 + dd4];
            float b00 = r0[dd4 * 4 + 0], b01 = r0[dd4 * 4 + 1];
            float b02 = r0[dd4 * 4 + 2], b03 = r0[dd4 * 4 + 3];
            float b10 = r1[dd4 * 4 + 0], b11 = r1[dd4 * 4 + 1];
            float b12 = r1[dd4 * 4 + 2], b13 = r1[dd4 * 4 + 3];
            acc[0][0] = fmaf(a0.x, b00, fmaf(a0.y, b01, fmaf(a0.z, b02, fmaf(a0.w, b03, acc[0][0]))));
            acc[0][1] = fmaf(a0.x, b10, fmaf(a0.y, b11, fmaf(a0.z, b12, fmaf(a0.w, b13, acc[0][1]))));
            acc[1][0] = fmaf(a1.x, b00, fmaf(a1.y, b01, fmaf(a1.z, b02, fmaf(a1.w, b03, acc[1][0]))));
            acc[1][1] = fmaf(a1.x, b10, fmaf(a1.y, b11, fmaf(a1.z, b12, fmaf(a1.w, b13, acc[1][1]))));
            acc[2][0] = fmaf(a2.x, b00, fmaf(a2.y, b01, fmaf(a2.z, b02, fmaf(a2.w, b03, acc[2][0]))));
            acc[2][1] = fmaf(a2.x, b10, fmaf(a2.y, b11, fmaf(a2.z, b12, fmaf(a2.w, b13, acc[2][1]))));
        }
        #pragma unroll
        for (int i = 0; i < 3; i++)
            #pragma unroll
            for (int j = 0; j < 2; j++) {
                int c = cg * 3 + i;
                int tl = tg * 2 + j;
                int t = t0 + tl;
                float v = acc[i][j];
                if (c < 4)       dts[c][tl] = v;
                else if (c < 20) g_BC[(size_t)(k * LL + t) * NS + (c - 4)].x = v;
                else             g_BC[(size_t)(k * LL + t) * NS + (c - 20)].y = v;
            }
    }
    __syncthreads();
    {
        int t = tid & 31;
        int w = tid >> 5;
        #pragma unroll
        for (int it = 0; it < 16; it++) {
            int d = w + 8 * it;
            float acc = dtb[d];
            #pragma unroll
            for (int r = 0; r < 4; r++)
                acc = fmaf(dtw[d * 4 + r], dts[r][t], acc);
            float delta = (acc > 20.f) ? acc : log1pf(__expf(acc));
            float u = xs[t][d];
            g_ddh[(size_t)(k * 128 + d) * LL + t0 + t] =
                __float22half2_rn(make_float2(delta, delta * u));
        }
    }
}

// ---------------- scan pass 1: smem B [t][n], half2 dd (4 steps/LDG.128) ----------------
__global__ void __launch_bounds__(512) k_scan1(const float* __restrict__ A_logs) {
    __shared__ float bb[LC * 16];          // 4 KB, [t][n]
    int tid = threadIdx.x;
    int wl = tid >> 5;
    int ln = tid & 31;
    int k = blockIdx.z, chunk = blockIdx.y, xh = blockIdx.x;
    int dp = xh * 16 + wl;
    int half = ln >> 4, n = ln & 15;
    int d = dp + (half << 6);
    int ch = k * 128 + d;
    int tbeg = chunk * LC;

    {
        const float4* src4 = (const float4*)(g_BC + (size_t)(k * LL + tbeg) * NS);
        if (tid < 512) {
            float4 v = src4[tid];
            bb[2 * tid]     = v.x;
            bb[2 * tid + 1] = v.z;
        }
    }
    __syncthreads();

    const uint4* pDD4 = (const uint4*)(g_ddh + (size_t)ch * LL + tbeg);
    float cA = -expf(A_logs[ch * 16 + n]) * 1.44269504f;
    float x = 0.f, sdelta = 0.f;
    #pragma unroll 4
    for (int s4 = 0; s4 < LC / 4; s4++) {
        uint4 q = pDD4[s4];
        float2 e0 = __half22float2(*reinterpret_cast<__half2*>(&q.x));
        float2 e1 = __half22float2(*reinterpret_cast<__half2*>(&q.y));
        float2 e2 = __half22float2(*reinterpret_cast<__half2*>(&q.z));
        float2 e3 = __half22float2(*reinterpret_cast<__half2*>(&q.w));
        float dA;
        asm("ex2.approx.ftz.f32 %0, %1;" : "=f"(dA) : "f"(e0.x * cA));
        x = fmaf(dA, x, e0.y * bb[(4 * s4 + 0) * 16 + n]);
        asm("ex2.approx.ftz.f32 %0, %1;" : "=f"(dA) : "f"(e1.x * cA));
        x = fmaf(dA, x, e1.y * bb[(4 * s4 + 1) * 16 + n]);
        asm("ex2.approx.ftz.f32 %0, %1;" : "=f"(dA) : "f"(e2.x * cA));
        x = fmaf(dA, x, e2.y * bb[(4 * s4 + 2) * 16 + n]);
        asm("ex2.approx.ftz.f32 %0, %1;" : "=f"(dA) : "f"(e3.x * cA));
        x = fmaf(dA, x, e3.y * bb[(4 * s4 + 3) * 16 + n]);
        sdelta += (e0.x + e1.x) + (e2.x + e3.x);
    }
    float ap;
    asm("ex2.approx.ftz.f32 %0, %1;" : "=f"(ap) : "f"(sdelta * cA));
    g_chk[((size_t)ch * CHK + chunk) * NS + n] = make_float2(x, ap);
}

// ---------------- scan pass 3: inline prefix fold, half2 dd, smem y-assembly ----------------
__global__ void __launch_bounds__(512) k_scan3(const float* __restrict__ A_logs) {
    __shared__ __align__(16) float BsmT[16 * 76];
    __shared__ __align__(16) float CsmT[16 * 76];
    __shared__ float xc[16][8][33];        // 16.9 KB
    __shared__ float ytile[8 * 33];
    int tid = threadIdx.x;
    int wl = tid >> 5;                     // 0..15
    int ln = tid & 31;
    int k = blockIdx.z, chunk = blockIdx.y, xh = blockIdx.x;
    int dp = xh * 16 + wl;
    int half = ln >> 4, n = ln & 15;
    int d = dp + (half << 6);
    int ch = k * 128 + d;
    int tbeg = chunk * LC;

    {
        const float2* srcBC = g_BC + (size_t)(k * LL + tbeg) * NS;
        for (int i = tid; i < LC * 16; i += 512) {
            int t = i >> 4, nn = i & 15;
            float2 v = srcBC[i];
            BsmT[nn * 76 + t] = v.x;
            CsmT[nn * 76 + t] = v.y;
        }
    }
    __syncthreads();

    const uint4* pDD4 = (const uint4*)(g_ddh + (size_t)ch * LL + tbeg);
    const float4* pB4 = (const float4*)(BsmT + n * 76);
    const float4* pC4 = (const float4*)(CsmT + n * 76);
    float cA = -expf(A_logs[ch * 16 + n]) * 1.44269504f;

    // inline prefix fold of preceding chunk summaries
    float x = 0.f;
    {
        const float2* pk = g_chk + (size_t)ch * CHK * NS + n;
        int c = 0;
        for (; c + 8 <= chunk; c += 8) {
            float2 f0 = pk[(c + 0) * NS], f1 = pk[(c + 1) * NS];
            float2 f2 = pk[(c + 2) * NS], f3 = pk[(c + 3) * NS];
            float2 f4 = pk[(c + 4) * NS], f5 = pk[(c + 5) * NS];
            float2 f6 = pk[(c + 6) * NS], f7 = pk[(c + 7) * NS];
            x = fmaf(f0.y, x, f0.x);
            x = fmaf(f1.y, x, f1.x);
            x = fmaf(f2.y, x, f2.x);
            x = fmaf(f3.y, x, f3.x);
            x = fmaf(f4.y, x, f4.x);
            x = fmaf(f5.y, x, f5.x);
            x = fmaf(f6.y, x, f6.x);
            x = fmaf(f7.y, x, f7.x);
        }
        for (; c < chunk; c++) {
            float2 f = pk[c * NS];
            x = fmaf(f.y, x, f.x);
        }
    }

    int rc = ln >> 4;
    int rj = (ln >> 1) & 7;
    int rh = ln & 1;
    int sr = tid >> 5;         // 0..15 (only 0..7 used for stores)
    int sc = tid & 31;
    int sd = xh * 16 + (sc & 15) + ((sc >> 4) << 6);
    float* ydst0 = g_y + (size_t)(k * LL + tbeg) * 128 + sd;

    for (int t0 = 0; t0 < LC; t0 += 8) {
        uint4 qa = pDD4[(t0 >> 2) + 0];
        uint4 qb = pDD4[(t0 >> 2) + 1];
        float4 b40 = pB4[(t0 >> 2) + 0];
        float4 b41 = pB4[(t0 >> 2) + 1];
        float4 c40 = pC4[(t0 >> 2) + 0];
        float4 c41 = pC4[(t0 >> 2) + 1];
        float2 e0 = __half22float2(*reinterpret_cast<__half2*>(&qa.x));
        float2 e1 = __half22float2(*reinterpret_cast<__half2*>(&qa.y));
        float2 e2 = __half22float2(*reinterpret_cast<__half2*>(&qa.z));
        float2 e3 = __half22float2(*reinterpret_cast<__half2*>(&qa.w));
        float2 e4 = __half22float2(*reinterpret_cast<__half2*>(&qb.x));
        float2 e5 = __half22float2(*reinterpret_cast<__half2*>(&qb.y));
        float2 e6 = __half22float2(*reinterpret_cast<__half2*>(&qb.z));
        float2 e7 = __half22float2(*reinterpret_cast<__half2*>(&qb.w));
        float dA;
        asm("ex2.approx.ftz.f32 %0, %1;" : "=f"(dA) : "f"(e0.x * cA));
        x = fmaf(dA, x, e0.y * b40.x);
        xc[wl][0][ln] = x * c40.x;
        asm("ex2.approx.ftz.f32 %0, %1;" : "=f"(dA) : "f"(e1.x * cA));
        x = fmaf(dA, x, e1.y * b40.y);
        xc[wl][1][ln] = x * c40.y;
        asm("ex2.approx.ftz.f32 %0, %1;" : "=f"(dA) : "f"(e2.x * cA));
        x = fmaf(dA, x, e2.y * b40.z);
        xc[wl][2][ln] = x * c40.z;
        asm("ex2.approx.ftz.f32 %0, %1;" : "=f"(dA) : "f"(e3.x * cA));
        x = fmaf(dA, x, e3.y * b40.w);
        xc[wl][3][ln] = x * c40.w;
        asm("ex2.approx.ftz.f32 %0, %1;" : "=f"(dA) : "f"(e4.x * cA));
        x = fmaf(dA, x, e4.y * b41.x);
        xc[wl][4][ln] = x * c41.x;
        asm("ex2.approx.ftz.f32 %0, %1;" : "=f"(dA) : "f"(e5.x * cA));
        x = fmaf(dA, x, e5.y * b41.y);
        xc[wl][5][ln] = x * c41.y;
        asm("ex2.approx.ftz.f32 %0, %1;" : "=f"(dA) : "f"(e6.x * cA));
        x = fmaf(dA, x, e6.y * b41.z);
        xc[wl][6][ln] = x * c41.z;
        asm("ex2.approx.ftz.f32 %0, %1;" : "=f"(dA) : "f"(e7.x * cA));
        x = fmaf(dA, x, e7.y * b41.w);
        xc[wl][7][ln] = x * c41.w;
        __syncwarp();
        float sum = 0.f;
        #pragma unroll
        for (int m = 0; m < 8; m++)
            sum += xc[wl][rj][rc * 16 + rh * 8 + m];
        sum += __shfl_xor_sync(0xffffffffu, sum, 1);
        if (rh == 0) ytile[rj * 33 + rc * 16 + wl] = sum;
        __syncthreads();
        if (tid < 256) ydst0[(size_t)(t0 + sr) * 128] = ytile[sr * 33 + sc];
        __syncthreads();
    }
}

// ---------------- combine: 4 concurrent positions per block ----------------
__global__ void __launch_bounds__(512) k_comb(const float* __restrict__ Ds,
                                              const float* __restrict__ ln_g,
                                              const float* __restrict__ ln_b,
                                              const float* __restrict__ W_out,
                                              float* __restrict__ out) {
    __shared__ __align__(16) float Wsm[64 * 132];
    __shared__ __align__(16) float gsm[4][132];
    __shared__ float red[4][8];
    __shared__ float mus[4][2];
    __shared__ int ism[6 * 16];
    int tid = threadIdx.x;
    int g = tid >> 7;
    int gt = tid & 127;
    for (int i = tid; i < 64 * 128; i += 512)
        Wsm[(i >> 7) * 132 + (i & 127)] = W_out[i];
    if (tid < 96) {
        int kk = tid >> 4, jj = tid & 15;
        ism[kk * 16 + jj] = iout_idx(kk, blockIdx.x * 16 + jj);
    }
    int d = gt;
    float dsum = 0.f;
    #pragma unroll
    for (int k = 0; k < 5; k++) dsum += Ds[k * 128 + d];
    float d5 = Ds[5 * 128 + d];
    float gg = ln_g[d], bb = ln_b[d];
    int lane = tid & 31;
    int wg = gt >> 5;
    int oo = (wg << 4) + (lane & 15);
    int hh2 = lane >> 4;
    __syncthreads();

    for (int it = 0; it < 4; it++) {
        int jj = it * 4 + g;
        int j = blockIdx.x * 16 + jj;
        float y = 0.f;
        #pragma unroll
        for (int k = 0; k < 6; k++)
            y += g_y[(size_t)(k * LL + ism[k * 16 + jj]) * 128 + d];
        int fl = ((63 - (j >> 6)) << 6) | (j & 63);
        y += dsum * g_xcT[j * 128 + d] + d5 * g_xcT[fl * 128 + d];
        float s1 = y, s2 = y * y;
        #pragma unroll
        for (int o = 16; o; o >>= 1) {
            s1 += __shfl_xor_sync(0xffffffffu, s1, o);
            s2 += __shfl_xor_sync(0xffffffffu, s2, o);
        }
        if (lane == 0) { red[g][wg] = s1; red[g][4 + wg] = s2; }
        __syncthreads();
        if (gt == 0) {
            float S1 = red[g][0] + red[g][1] + red[g][2] + red[g][3];
            float S2 = red[g][4] + red[g][5] + red[g][6] + red[g][7];
            float mu = S1 * (1.f / 128.f);
            float var = S2 * (1.f / 128.f) - mu * mu;
            mus[g][0] = mu;
            mus[g][1] = rsqrtf(var + 1e-5f);
        }
        __syncthreads();
        float yn = (y - mus[g][0]) * mus[g][1] * gg + bb;
        float z = g_z[j * 128 + d];
        gsm[g][d] = yn * (z / (1.f + __expf(-z)));
        __syncthreads();
        {
            float acc = 0.f;
            const float4* wrow = (const float4*)(Wsm + oo * 132 + (hh2 << 6));
            const float4* grow = (const float4*)(gsm[g] + (hh2 << 6));
            #pragma unroll
            for (int q = 0; q < 16; q++) {
                float4 wv = wrow[q];
                float4 gv = grow[q];
                acc = fmaf(wv.x, gv.x, fmaf(wv.y, gv.y, fmaf(wv.z, gv.z, fmaf(wv.w, gv.w, acc))));
            }
            acc += __shfl_xor_sync(0xffffffffu, acc, 16);
            if (hh2 == 0) out[j * 64 + oo] = acc;
        }
        __syncthreads();
    }
}

// ---------------- launch ----------------
extern "C" void kernel_launch(void* const* d_in, const int* in_sizes, int n_in,
                              void* d_out, int out_size) {
    const float* x        = (const float*)d_in[0];
    const float* W_in     = (const float*)d_in[1];
    const float* conv_w   = (const float*)d_in[2];
    const float* conv_b   = (const float*)d_in[3];
    const float* x_proj_w = (const float*)d_in[4];
    const float* dt_w     = (const float*)d_in[5];
    const float* dt_b     = (const float*)d_in[6];
    const float* A_logs   = (const float*)d_in[7];
    const float* Ds       = (const float*)d_in[8];
    const float* ln_g     = (const float*)d_in[9];
    const float* ln_b     = (const float*)d_in[10];
    const float* W_out    = (const float*)d_in[11];
    float* out = (float*)d_out;

    {
        dim3 g(128, 2);
        k_inproj<<<g, 256>>>(x, W_in);
    }
    k_conv<<<(LL * 32) / 256, 256>>>(conv_w, conv_b);
    {
        dim3 g(LL / 32, KDIR);
        k_proj<<<g, 256>>>(x_proj_w, dt_w, dt_b);
    }
    {
        dim3 gs(4, CHK, KDIR);
        k_scan1<<<gs, 512>>>(A_logs);
        k_scan3<<<gs, 512>>>(A_logs);
    }
    k_comb<<<256, 512>>>(Ds, ln_g, ln_b, W_out, out);
}

// round 15
// speedup vs baseline: 1.1369x; 1.0018x over previous
#include <cuda_runtime.h>
#include <cuda_bf16.h>
#include <cuda_fp16.h>
#include <math.h>

#define KDIR 6
#define LL 4096
#define DI 128
#define NS 16
#define DTR 4
#define NCH (KDIR * DI)
#define CHK 64
#define LC  (LL / CHK)         // 64

// ---------------- scratch ----------------
__device__ float   g_xx[LL * DI];
__device__ float   g_z [LL * DI];
__device__ float   g_xcT[LL * DI];
__device__ __half2 g_BCh[KDIR * LL * NS];   // (B,C) fp16 packed, [k][t][n]
__device__ __half2 g_ddh[KDIR * DI * LL];   // (delta, delta*u) fp16, [k][d][t]
__device__ __half  g_yh[KDIR * LL * DI];    // y fp16, [k][t][d]
__device__ float2  g_chk [NCH * CHK * NS];  // per-chunk (xf, aprod)

// ---------------- closed-form diagonal permutation ----------------
__device__ __forceinline__ int dg_low(int r) {
    int dg = (int)((sqrtf((float)(8 * r + 1)) - 1.f) * 0.5f);
    while (((dg + 1) * (dg + 2)) >> 1 <= r) dg++;
    while ((dg * (dg + 1)) >> 1 > r) dg--;
    return dg;
}
__device__ __forceinline__ int diag_t(int r) {
    int i, dg;
    if (r < 2080) { dg = dg_low(r); i = r - ((dg * (dg + 1)) >> 1); }
    else {
        int q = 4095 - r;
        int dgm = dg_low(q);
        int p = q - ((dgm * (dgm + 1)) >> 1);
        i = 63 - p;
        dg = 126 - dgm;
    }
    int j = dg - i;
    return (i << 6) | j;
}
__device__ __forceinline__ int rev_idx(int t) {
    int i = t >> 6, c = t & 63, dg = i + c;
    int cum = (dg < 64) ? ((dg * (dg + 1)) >> 1)
                        : 4096 - (((127 - dg) * (128 - dg)) >> 1);
    int lo = dg - 63; if (lo < 0) lo = 0;
    return cum + i - lo;
}
__device__ __forceinline__ int sin_idx(int k, int t) {
    switch (k) {
        case 0: return t;
        case 1: return ((t & 63) << 6) | (t >> 6);
        case 2: return 4095 - t;
        case 3: { int t2 = 4095 - t; return ((t2 & 63) << 6) | (t2 >> 6); }
        case 4: return diag_t(t);
        default: return diag_t(t) ^ 63;
    }
}
__device__ __forceinline__ int iout_idx(int k, int j) {
    switch (k) {
        case 0: return j;
        case 1: return ((j & 63) << 6) | (j >> 6);
        case 2: return 4095 - j;
        case 3: return 4095 - (((j & 63) << 6) | (j >> 6));
        case 4: return rev_idx(j);
        default: return rev_idx(4095 - j);
    }
}

// ---------------- in_proj GEMM: blockIdx.y = output half ----------------
__global__ void __launch_bounds__(256) k_inproj(const float* __restrict__ x,
                                                const float* __restrict__ W_in) {
    __shared__ float Wsm[128 * 65];
    __shared__ float xsm[32 * 65];
    int tid = threadIdx.x;
    int l0 = blockIdx.x * 32;
    int ot = blockIdx.y;
    for (int i = tid; i < 32 * 64; i += 256)
        xsm[(i >> 6) * 65 + (i & 63)] = x[(l0 + (i >> 6)) * 64 + (i & 63)];
    for (int i = tid; i < 128 * 64; i += 256)
        Wsm[(i >> 6) * 65 + (i & 63)] = W_in[(ot * 128 + (i >> 6)) * 64 + (i & 63)];
    int og = tid & 31;
    int lg = tid >> 5;
    __syncthreads();
    float acc[4][4];
    #pragma unroll
    for (int i = 0; i < 4; i++)
        #pragma unroll
        for (int ii = 0; ii < 4; ii++) acc[i][ii] = 0.f;
    for (int c = 0; c < 64; c++) {
        float wv[4], xv[4];
        #pragma unroll
        for (int i = 0; i < 4; i++)  wv[i]  = Wsm[(og + 32 * i) * 65 + c];
        #pragma unroll
        for (int ii = 0; ii < 4; ii++) xv[ii] = xsm[(lg + 8 * ii) * 65 + c];
        #pragma unroll
        for (int i = 0; i < 4; i++)
            #pragma unroll
            for (int ii = 0; ii < 4; ii++)
                acc[i][ii] = fmaf(wv[i], xv[ii], acc[i][ii]);
    }
    float* dst = (ot == 0) ? g_xx : g_z;
    #pragma unroll
    for (int i = 0; i < 4; i++)
        #pragma unroll
        for (int ii = 0; ii < 4; ii++)
            dst[(l0 + lg + 8 * ii) * 128 + og + 32 * i] = acc[i][ii];
}

// ---------------- depthwise 3x3 conv + bias + SiLU (float4 per thread) ----------------
__global__ void __launch_bounds__(256) k_conv(const float* __restrict__ conv_w,
                                              const float* __restrict__ conv_b) {
    __shared__ float4 cw[9 * 32];
    __shared__ float4 cb[32];
    int tid = threadIdx.x;
    for (int i = tid; i < 9 * 32; i += 256) {
        int tap = i >> 5, d4 = i & 31;
        cw[i] = make_float4(conv_w[(4 * d4 + 0) * 9 + tap], conv_w[(4 * d4 + 1) * 9 + tap],
                            conv_w[(4 * d4 + 2) * 9 + tap], conv_w[(4 * d4 + 3) * 9 + tap]);
    }
    if (tid < 32) cb[tid] = ((const float4*)conv_b)[tid];
    __syncthreads();
    int idx = blockIdx.x * 256 + tid;    // < LL*32
    int d4 = idx & 31;
    int l = idx >> 5;
    int h = l >> 6, w = l & 63;
    float4 acc = cb[d4];
    const float4* xx4 = (const float4*)g_xx;
    #pragma unroll
    for (int kh = -1; kh <= 1; kh++) {
        int hh = h + kh;
        if ((unsigned)hh >= 64u) continue;
        #pragma unroll
        for (int kw = -1; kw <= 1; kw++) {
            int wc = w + kw;
            if ((unsigned)wc >= 64u) continue;
            float4 v = xx4[((hh << 6) | wc) * 32 + d4];
            float4 cc = cw[((kh + 1) * 3 + (kw + 1)) * 32 + d4];
            acc.x = fmaf(cc.x, v.x, acc.x);
            acc.y = fmaf(cc.y, v.y, acc.y);
            acc.z = fmaf(cc.z, v.z, acc.z);
            acc.w = fmaf(cc.w, v.w, acc.w);
        }
    }
    acc.x = acc.x / (1.f + __expf(-acc.x));
    acc.y = acc.y / (1.f + __expf(-acc.y));
    acc.z = acc.z / (1.f + __expf(-acc.z));
    acc.w = acc.w / (1.f + __expf(-acc.w));
    ((float4*)g_xcT)[l * 32 + d4] = acc;
}

// ---------------- projection + fused delta (half outputs) ----------------
__global__ void __launch_bounds__(256) k_proj(const float* __restrict__ x_proj_w,
                                              const float* __restrict__ dt_w,
                                              const float* __restrict__ dt_b) {
    __shared__ float xs[32][129];
    __shared__ __align__(16) float Ps[36 * 128];
    __shared__ float dts[4][32];
    __shared__ float dtw[128 * 4];
    __shared__ float dtb[128];
    __shared__ int sidx[32];
    int k  = blockIdx.y;
    int t0 = blockIdx.x * 32;
    int tid = threadIdx.x;
    if (tid < 32) sidx[tid] = sin_idx(k, t0 + tid);
    __syncthreads();
    for (int i = tid; i < 36 * 128; i += 256)
        Ps[i] = x_proj_w[k * 36 * 128 + i];
    for (int i = tid; i < 512; i += 256)
        dtw[i] = dt_w[k * 512 + i];
    if (tid < 128) dtb[tid] = dt_b[k * 128 + tid];
    {
        int lane = tid & 31;
        for (int r = tid >> 5; r < 32; r += 8) {
            int s = sidx[r];
            const float4* src = (const float4*)(g_xcT + s * 128);
            float4 v = src[lane];
            xs[r][lane * 4 + 0] = v.x;
            xs[r][lane * 4 + 1] = v.y;
            xs[r][lane * 4 + 2] = v.z;
            xs[r][lane * 4 + 3] = v.w;
        }
    }
    __syncthreads();
    if (tid < 192) {
        int cg = tid >> 4;
        int tg = tid & 15;
        float acc[3][2] = {{0.f,0.f},{0.f,0.f},{0.f,0.f}};
        const float4* Ps4 = (const float4*)Ps;
        const float* r0 = &xs[tg * 2 + 0][0];
        const float* r1 = &xs[tg * 2 + 1][0];
        for (int dd4 = 0; dd4 < 32; dd4++) {
            float4 a0 = Ps4[(cg * 3 + 0) * 32 + dd4];
            float4 a1 = Ps4[(cg * 3 + 1) * 32 + dd4];
            float4 a2 = Ps4[(cg * 3 + 2) * 32 + dd4];
            float b00 = r0[dd4 * 4 + 0], b01 = r0[dd4 * 4 + 1];
            float b02 = r0[dd4 * 4 + 2], b03 = r0[dd4 * 4 + 3];
            float b10 = r1[dd4 * 4 + 0], b11 = r1[dd4 * 4 + 1];
            float b12 = r1[dd4 * 4 + 2], b13 = r1[dd4 * 4 + 3];
            acc[0][0] = fmaf(a0.x, b00, fmaf(a0.y, b01, fmaf(a0.z, b02, fmaf(a0.w, b03, acc[0][0]))));
            acc[0][1] = fmaf(a0.x, b10, fmaf(a0.y, b11, fmaf(a0.z, b12, fmaf(a0.w, b13, acc[0][1]))));
            acc[1][0] = fmaf(a1.x, b00, fmaf(a1.y, b01, fmaf(a1.z, b02, fmaf(a1.w, b03, acc[1][0]))));
            acc[1][1] = fmaf(a1.x, b10, fmaf(a1.y, b11, fmaf(a1.z, b12, fmaf(a1.w, b13, acc[1][1]))));
            acc[2][0] = fmaf(a2.x, b00, fmaf(a2.y, b01, fmaf(a2.z, b02, fmaf(a2.w, b03, acc[2][0]))));
            acc[2][1] = fmaf(a2.x, b10, fmaf(a2.y, b11, fmaf(a2.z, b12, fmaf(a2.w, b13, acc[2][1]))));
        }
        __half* bch = (__half*)g_BCh;
        #pragma unroll
        for (int i = 0; i < 3; i++)
            #pragma unroll
            for (int j = 0; j < 2; j++) {
                int c = cg * 3 + i;
                int tl = tg * 2 + j;
                int t = t0 + tl;
                float v = acc[i][j];
                if (c < 4)       dts[c][tl] = v;
                else if (c < 20) bch[2 * ((size_t)(k * LL + t) * NS + (c - 4))] = __float2half_rn(v);
                else             bch[2 * ((size_t)(k * LL + t) * NS + (c - 20)) + 1] = __float2half_rn(v);
            }
    }
    __syncthreads();
    {
        int t = tid & 31;
        int w = tid >> 5;
        #pragma unroll
        for (int it = 0; it < 16; it++) {
            int d = w + 8 * it;
            float acc = dtb[d];
            #pragma unroll
            for (int r = 0; r < 4; r++)
                acc = fmaf(dtw[d * 4 + r], dts[r][t], acc);
            float delta = (acc > 20.f) ? acc : log1pf(__expf(acc));
            float u = xs[t][d];
            g_ddh[(size_t)(k * 128 + d) * LL + t0 + t] =
                __float22half2_rn(make_float2(delta, delta * u));
        }
    }
}

// ---------------- scan pass 1: fp16 staging, half2 dd ----------------
__global__ void __launch_bounds__(512) k_scan1(const float* __restrict__ A_logs) {
    __shared__ float bb[LC * 16];          // 4 KB, [t][n]
    int tid = threadIdx.x;
    int wl = tid >> 5;
    int ln = tid & 31;
    int k = blockIdx.z, chunk = blockIdx.y, xh = blockIdx.x;
    int dp = xh * 16 + wl;
    int half = ln >> 4, n = ln & 15;
    int d = dp + (half << 6);
    int ch = k * 128 + d;
    int tbeg = chunk * LC;

    {
        const uint4* src4 = (const uint4*)(g_BCh + (size_t)(k * LL + tbeg) * NS);
        if (tid < 256) {
            uint4 v = src4[tid];   // 4 (B,C) half2 pairs
            bb[4 * tid + 0] = __low2float(*reinterpret_cast<__half2*>(&v.x));
            bb[4 * tid + 1] = __low2float(*reinterpret_cast<__half2*>(&v.y));
            bb[4 * tid + 2] = __low2float(*reinterpret_cast<__half2*>(&v.z));
            bb[4 * tid + 3] = __low2float(*reinterpret_cast<__half2*>(&v.w));
        }
    }
    __syncthreads();

    const uint4* pDD4 = (const uint4*)(g_ddh + (size_t)ch * LL + tbeg);
    float cA = -expf(A_logs[ch * 16 + n]) * 1.44269504f;
    float x = 0.f, sdelta = 0.f;
    #pragma unroll 4
    for (int s4 = 0; s4 < LC / 4; s4++) {
        uint4 q = pDD4[s4];
        float2 e0 = __half22float2(*reinterpret_cast<__half2*>(&q.x));
        float2 e1 = __half22float2(*reinterpret_cast<__half2*>(&q.y));
        float2 e2 = __half22float2(*reinterpret_cast<__half2*>(&q.z));
        float2 e3 = __half22float2(*reinterpret_cast<__half2*>(&q.w));
        float dA;
        asm("ex2.approx.ftz.f32 %0, %1;" : "=f"(dA) : "f"(e0.x * cA));
        x = fmaf(dA, x, e0.y * bb[(4 * s4 + 0) * 16 + n]);
        asm("ex2.approx.ftz.f32 %0, %1;" : "=f"(dA) : "f"(e1.x * cA));
        x = fmaf(dA, x, e1.y * bb[(4 * s4 + 1) * 16 + n]);
        asm("ex2.approx.ftz.f32 %0, %1;" : "=f"(dA) : "f"(e2.x * cA));
        x = fmaf(dA, x, e2.y * bb[(4 * s4 + 2) * 16 + n]);
        asm("ex2.approx.ftz.f32 %0, %1;" : "=f"(dA) : "f"(e3.x * cA));
        x = fmaf(dA, x, e3.y * bb[(4 * s4 + 3) * 16 + n]);
        sdelta += (e0.x + e1.x) + (e2.x + e3.x);
    }
    float ap;
    asm("ex2.approx.ftz.f32 %0, %1;" : "=f"(ap) : "f"(sdelta * cA));
    g_chk[((size_t)ch * CHK + chunk) * NS + n] = make_float2(x, ap);
}

// ---------------- scan pass 3: fp16 staging/outputs, inline prefix fold ----------------
__global__ void __launch_bounds__(512) k_scan3(const float* __restrict__ A_logs) {
    __shared__ __align__(16) float BsmT[16 * 76];
    __shared__ __align__(16) float CsmT[16 * 76];
    __shared__ float xc[16][8][33];        // 16.9 KB
    __shared__ float ytile[8 * 33];
    int tid = threadIdx.x;
    int wl = tid >> 5;                     // 0..15
    int ln = tid & 31;
    int k = blockIdx.z, chunk = blockIdx.y, xh = blockIdx.x;
    int dp = xh * 16 + wl;
    int half = ln >> 4, n = ln & 15;
    int d = dp + (half << 6);
    int ch = k * 128 + d;
    int tbeg = chunk * LC;

    {
        const uint4* src4 = (const uint4*)(g_BCh + (size_t)(k * LL + tbeg) * NS);
        if (tid < 256) {
            uint4 v = src4[tid];
            int base = 4 * tid;
            #pragma unroll
            for (int q = 0; q < 4; q++) {
                unsigned w = (q == 0) ? v.x : (q == 1) ? v.y : (q == 2) ? v.z : v.w;
                float2 bc = __half22float2(*reinterpret_cast<__half2*>(&w));
                int idx = base + q;
                int t = idx >> 4, nn = idx & 15;
                BsmT[nn * 76 + t] = bc.x;
                CsmT[nn * 76 + t] = bc.y;
            }
        }
    }
    __syncthreads();

    const uint4* pDD4 = (const uint4*)(g_ddh + (size_t)ch * LL + tbeg);
    const float4* pB4 = (const float4*)(BsmT + n * 76);
    const float4* pC4 = (const float4*)(CsmT + n * 76);
    float cA = -expf(A_logs[ch * 16 + n]) * 1.44269504f;

    // inline prefix fold of preceding chunk summaries
    float x = 0.f;
    {
        const float2* pk = g_chk + (size_t)ch * CHK * NS + n;
        int c = 0;
        for (; c + 8 <= chunk; c += 8) {
            float2 f0 = pk[(c + 0) * NS], f1 = pk[(c + 1) * NS];
            float2 f2 = pk[(c + 2) * NS], f3 = pk[(c + 3) * NS];
            float2 f4 = pk[(c + 4) * NS], f5 = pk[(c + 5) * NS];
            float2 f6 = pk[(c + 6) * NS], f7 = pk[(c + 7) * NS];
            x = fmaf(f0.y, x, f0.x);
            x = fmaf(f1.y, x, f1.x);
            x = fmaf(f2.y, x, f2.x);
            x = fmaf(f3.y, x, f3.x);
            x = fmaf(f4.y, x, f4.x);
            x = fmaf(f5.y, x, f5.x);
            x = fmaf(f6.y, x, f6.x);
            x = fmaf(f7.y, x, f7.x);
        }
        for (; c < chunk; c++) {
            float2 f = pk[c * NS];
            x = fmaf(f.y, x, f.x);
        }
    }

    int rc = ln >> 4;
    int rj = (ln >> 1) & 7;
    int rh = ln & 1;
    // fp16 y store mapping: 128 threads, half2 of adjacent d
    int sr = tid >> 4;          // 0..7 for tid<128
    int p  = tid & 15;
    int scp = (p < 8) ? (2 * p) : (16 + 2 * (p - 8));
    int sdp = (p < 8) ? (xh * 16 + 2 * p) : (64 + xh * 16 + 2 * (p - 8));
    __half2* ydst0 = (__half2*)g_yh + (size_t)(k * LL + tbeg) * 64 + (sdp >> 1);

    for (int t0 = 0; t0 < LC; t0 += 8) {
        uint4 qa = pDD4[(t0 >> 2) + 0];
        uint4 qb = pDD4[(t0 >> 2) + 1];
        float4 b40 = pB4[(t0 >> 2) + 0];
        float4 b41 = pB4[(t0 >> 2) + 1];
        float4 c40 = pC4[(t0 >> 2) + 0];
        float4 c41 = pC4[(t0 >> 2) + 1];
        float2 e0 = __half22float2(*reinterpret_cast<__half2*>(&qa.x));
        float2 e1 = __half22float2(*reinterpret_cast<__half2*>(&qa.y));
        float2 e2 = __half22float2(*reinterpret_cast<__half2*>(&qa.z));
        float2 e3 = __half22float2(*reinterpret_cast<__half2*>(&qa.w));
        float2 e4 = __half22float2(*reinterpret_cast<__half2*>(&qb.x));
        float2 e5 = __half22float2(*reinterpret_cast<__half2*>(&qb.y));
        float2 e6 = __half22float2(*reinterpret_cast<__half2*>(&qb.z));
        float2 e7 = __half22float2(*reinterpret_cast<__half2*>(&qb.w));
        float dA;
        asm("ex2.approx.ftz.f32 %0, %1;" : "=f"(dA) : "f"(e0.x * cA));
        x = fmaf(dA, x, e0.y * b40.x);
        xc[wl][0][ln] = x * c40.x;
        asm("ex2.approx.ftz.f32 %0, %1;" : "=f"(dA) : "f"(e1.x * cA));
        x = fmaf(dA, x, e1.y * b40.y);
        xc[wl][1][ln] = x * c40.y;
        asm("ex2.approx.ftz.f32 %0, %1;" : "=f"(dA) : "f"(e2.x * cA));
        x = fmaf(dA, x, e2.y * b40.z);
        xc[wl][2][ln] = x * c40.z;
        asm("ex2.approx.ftz.f32 %0, %1;" : "=f"(dA) : "f"(e3.x * cA));
        x = fmaf(dA, x, e3.y * b40.w);
        xc[wl][3][ln] = x * c40.w;
        asm("ex2.approx.ftz.f32 %0, %1;" : "=f"(dA) : "f"(e4.x * cA));
        x = fmaf(dA, x, e4.y * b41.x);
        xc[wl][4][ln] = x * c41.x;
        asm("ex2.approx.ftz.f32 %0, %1;" : "=f"(dA) : "f"(e5.x * cA));
        x = fmaf(dA, x, e5.y * b41.y);
        xc[wl][5][ln] = x * c41.y;
        asm("ex2.approx.ftz.f32 %0, %1;" : "=f"(dA) : "f"(e6.x * cA));
        x = fmaf(dA, x, e6.y * b41.z);
        xc[wl][6][ln] = x * c41.z;
        asm("ex2.approx.ftz.f32 %0, %1;" : "=f"(dA) : "f"(e7.x * cA));
        x = fmaf(dA, x, e7.y * b41.w);
        xc[wl][7][ln] = x * c41.w;
        __syncwarp();
        float sum = 0.f;
        #pragma unroll
        for (int m = 0; m < 8; m++)
            sum += xc[wl][rj][rc * 16 + rh * 8 + m];
        sum += __shfl_xor_sync(0xffffffffu, sum, 1);
        if (rh == 0) ytile[rj * 33 + rc * 16 + wl] = sum;
        __syncthreads();
        if (tid < 128)
            ydst0[(size_t)(t0 + sr) * 64] =
                __floats2half2_rn(ytile[sr * 33 + scp], ytile[sr * 33 + scp + 1]);
        __syncthreads();
    }
}

// ---------------- combine: 4 concurrent positions per block ----------------
__global__ void __launch_bounds__(512) k_comb(const float* __restrict__ Ds,
                                              const float* __restrict__ ln_g,
                                              const float* __restrict__ ln_b,
                                              const float* __restrict__ W_out,
                                              float* __restrict__ out) {
    __shared__ __align__(16) float Wsm[64 * 132];
    __shared__ __align__(16) float gsm[4][132];
    __shared__ float red[4][8];
    __shared__ float mus[4][2];
    __shared__ int ism[6 * 16];
    int tid = threadIdx.x;
    int g = tid >> 7;
    int gt = tid & 127;
    for (int i = tid; i < 64 * 128; i += 512)
        Wsm[(i >> 7) * 132 + (i & 127)] = W_out[i];
    if (tid < 96) {
        int kk = tid >> 4, jj = tid & 15;
        ism[kk * 16 + jj] = iout_idx(kk, blockIdx.x * 16 + jj);
    }
    int d = gt;
    float dsum = 0.f;
    #pragma unroll
    for (int k = 0; k < 5; k++) dsum += Ds[k * 128 + d];
    float d5 = Ds[5 * 128 + d];
    float gg = ln_g[d], bb = ln_b[d];
    int lane = tid & 31;
    int wg = gt >> 5;
    int oo = (wg << 4) + (lane & 15);
    int hh2 = lane >> 4;
    __syncthreads();

    for (int it = 0; it < 4; it++) {
        int jj = it * 4 + g;
        int j = blockIdx.x * 16 + jj;
        float y = 0.f;
        #pragma unroll
        for (int k = 0; k < 6; k++)
            y += __half2float(g_yh[(size_t)(k * LL + ism[k * 16 + jj]) * 128 + d]);
        int fl = ((63 - (j >> 6)) << 6) | (j & 63);
        y += dsum * g_xcT[j * 128 + d] + d5 * g_xcT[fl * 128 + d];
        float s1 = y, s2 = y * y;
        #pragma unroll
        for (int o = 16; o; o >>= 1) {
            s1 += __shfl_xor_sync(0xffffffffu, s1, o);
            s2 += __shfl_xor_sync(0xffffffffu, s2, o);
        }
        if (lane == 0) { red[g][wg] = s1; red[g][4 + wg] = s2; }
        __syncthreads();
        if (gt == 0) {
            float S1 = red[g][0] + red[g][1] + red[g][2] + red[g][3];
            float S2 = red[g][4] + red[g][5] + red[g][6] + red[g][7];
            float mu = S1 * (1.f / 128.f);
            float var = S2 * (1.f / 128.f) - mu * mu;
            mus[g][0] = mu;
            mus[g][1] = rsqrtf(var + 1e-5f);
        }
        __syncthreads();
        float yn = (y - mus[g][0]) * mus[g][1] * gg + bb;
        float z = g_z[j * 128 + d];
        gsm[g][d] = yn * (z / (1.f + __expf(-z)));
        __syncthreads();
        {
            float acc = 0.f;
            const float4* wrow = (const float4*)(Wsm + oo * 132 + (hh2 << 6));
            const float4* grow = (const float4*)(gsm[g] + (hh2 << 6));
            #pragma unroll
            for (int q = 0; q < 16; q++) {
                float4 wv = wrow[q];
                float4 gv = grow[q];
                acc = fmaf(wv.x, gv.x, fmaf(wv.y, gv.y, fmaf(wv.z, gv.z, fmaf(wv.w, gv.w, acc))));
            }
            acc += __shfl_xor_sync(0xffffffffu, acc, 16);
            if (hh2 == 0) out[j * 64 + oo] = acc;
        }
        __syncthreads();
    }
}

// ---------------- launch ----------------
extern "C" void kernel_launch(void* const* d_in, const int* in_sizes, int n_in,
                              void* d_out, int out_size) {
    const float* x        = (const float*)d_in[0];
    const float* W_in     = (const float*)d_in[1];
    const float* conv_w   = (const float*)d_in[2];
    const float* conv_b   = (const float*)d_in[3];
    const float* x_proj_w = (const float*)d_in[4];
    const float* dt_w     = (const float*)d_in[5];
    const float* dt_b     = (const float*)d_in[6];
    const float* A_logs   = (const float*)d_in[7];
    const float* Ds       = (const float*)d_in[8];
    const float* ln_g     = (const float*)d_in[9];
    const float* ln_b     = (const float*)d_in[10];
    const float* W_out    = (const float*)d_in[11];
    float* out = (float*)d_out;

    {
        dim3 g(128, 2);
        k_inproj<<<g, 256>>>(x, W_in);
    }
    k_conv<<<(LL * 32) / 256, 256>>>(conv_w, conv_b);
    {
        dim3 g(LL / 32, KDIR);
        k_proj<<<g, 256>>>(x_proj_w, dt_w, dt_b);
    }
    {
        dim3 gs(4, CHK, KDIR);
        k_scan1<<<gs, 512>>>(A_logs);
        k_scan3<<<gs, 512>>>(A_logs);
    }
    k_comb<<<256, 512>>>(Ds, ln_g, ln_b, W_out, out);
}